// round 15
// baseline (speedup 1.0000x reference)
#include <cuda_runtime.h>
#include <cuda_bf16.h>
#include <math.h>

#define NB 4
#define ND 128
#define NT 4096
#define LOG2E 1.4426950408889634f

__device__ __nv_bfloat16 g_QKb[NB * NT * 128];  // per row: [Q(64)*log2e | K(64)] bf16
__device__ __nv_bfloat16 g_Vb[NB * NT * 128];   // V bf16
__device__ __nv_bfloat16 g_Wb[256 * 128];       // [Wq*log2e | Wk | Wv] bf16
__device__ float g_biasf[256];                  // [bq*log2e | bk | bv]
__device__ float g_colsum[NB * NT];
__device__ float g_inv[NB * NT];                // 1/(8*colsum)
__device__ int   g_cnt[NB * 64];                // per t-tile completion counters

// ---------------------------------------------------------------------------
__device__ __forceinline__ void mma16(float* d, const unsigned* a, const unsigned* b) {
    asm volatile(
        "mma.sync.aligned.m16n8k16.row.col.f32.bf16.bf16.f32 "
        "{%0,%1,%2,%3}, {%4,%5,%6,%7}, {%8,%9}, {%0,%1,%2,%3};\n"
        : "+f"(d[0]), "+f"(d[1]), "+f"(d[2]), "+f"(d[3])
        : "r"(a[0]), "r"(a[1]), "r"(a[2]), "r"(a[3]), "r"(b[0]), "r"(b[1]));
}
__device__ __forceinline__ unsigned packbf(float lo, float hi) {
    unsigned r;
    asm("cvt.rn.bf16x2.f32 %0, %1, %2;" : "=r"(r) : "f"(hi), "f"(lo));
    return r;
}
__device__ __forceinline__ void ldsm4(unsigned* r, unsigned addr) {
    asm volatile("ldmatrix.sync.aligned.m8n8.x4.shared.b16 {%0,%1,%2,%3}, [%4];"
                 : "=r"(r[0]), "=r"(r[1]), "=r"(r[2]), "=r"(r[3]) : "r"(addr));
}
__device__ __forceinline__ void ldsm4t(unsigned* r, unsigned addr) {
    asm volatile("ldmatrix.sync.aligned.m8n8.x4.trans.shared.b16 {%0,%1,%2,%3}, [%4];"
                 : "=r"(r[0]), "=r"(r[1]), "=r"(r[2]), "=r"(r[3]) : "r"(addr));
}
__device__ __forceinline__ void cpa16(unsigned saddr, const void* gsrc) {
    asm volatile("cp.async.cg.shared.global [%0], [%1], 16;" :: "r"(saddr), "l"(gsrc));
}
__device__ __forceinline__ void cpcommit() { asm volatile("cp.async.commit_group;"); }
template <int N>
__device__ __forceinline__ void cpwait() { asm volatile("cp.async.wait_group %0;" :: "n"(N)); }
__device__ __forceinline__ unsigned ldu32(const __nv_bfloat16* p) { return *(const unsigned*)p; }
__device__ __forceinline__ unsigned swz(unsigned base, int row, int chunk) {
    return base + ((row * 16 + (chunk ^ (row & 7))) << 4);
}

// ---------------------------------------------------------------------------
// Convert weights to bf16 once; fold log2e into Wq/bq.
__global__ void wconv_kernel(const float* __restrict__ Wq, const float* __restrict__ bq,
                             const float* __restrict__ Wk, const float* __restrict__ bk,
                             const float* __restrict__ Wv, const float* __restrict__ bv) {
    int i = blockIdx.x * 256 + threadIdx.x;      // [0, 32768)
    int n = i >> 7, d = i & 127;
    float v;
    if (n < 64)       v = Wq[n * 128 + d] * LOG2E;
    else if (n < 128) v = Wk[(n - 64) * 128 + d];
    else              v = Wv[(n - 128) * 128 + d];
    g_Wb[i] = __float2bfloat16(v);
    if (i < 256) {
        float bb;
        if (i < 64)       bb = bq[i] * LOG2E;
        else if (i < 128) bb = bk[i - 64];
        else              bb = bv[i - 128];
        g_biasf[i] = bb;
    }
}

// ---------------------------------------------------------------------------
// QKV: grid (2 n-halves, 512 m-half-tiles). W via cp.async (preconverted bf16).
__global__ __launch_bounds__(256) void qkv_kernel(const float* __restrict__ mb) {
    __shared__ __align__(16) __nv_bfloat16 Xb[32 * 128];   // swizzled [r][d]
    __shared__ __align__(16) __nv_bfloat16 Wb[128 * 128];  // swizzled [n][d]
    int n0 = blockIdx.x * 128;
    int m0 = blockIdx.y * 32;
    int b = m0 >> 12, t0 = m0 & (NT - 1);
    const float* x = mb + (size_t)b * ND * NT;
    int tid = threadIdx.x, lane = tid & 31, w = tid >> 5;
    int g = lane >> 2, tg = lane & 3;
    int wr = w & 1, wc = w >> 1;

    if (blockIdx.x == 0) {
        if (tid < 32) g_colsum[m0 + tid] = 0.0f;
        if (tid == 32 && !(m0 & 32)) g_cnt[m0 >> 6] = 0;
    }

    unsigned xb = (unsigned)__cvta_generic_to_shared(Xb);
    unsigned wb = (unsigned)__cvta_generic_to_shared(Wb);

#pragma unroll
    for (int i = 0; i < 8; i++) {
        int idx = tid + 256 * i;
        int n = idx >> 4, c = idx & 15;
        cpa16(swz(wb, n, c), &g_Wb[(size_t)(n0 + n) * 128 + c * 8]);
    }
    cpcommit();

#pragma unroll
    for (int i = 0; i < 8; i++) {
        int idx = tid + 256 * i;
        int r = idx & 31, d2 = idx >> 5;
        float v0 = x[(2 * d2) * NT + t0 + r];
        float v1 = x[(2 * d2 + 1) * NT + t0 + r];
        *(unsigned*)&Xb[(r * 16 + ((d2 >> 2) ^ (r & 7))) * 8 + (d2 & 3) * 2] = packbf(v0, v1);
    }
    cpwait<0>();
    __syncthreads();

    int arow = (lane & 7) + ((lane >> 3) & 1) * 8;
    int achk = lane >> 4;
    int krow = ((lane >> 4) << 3) + (lane & 7);
    int kchk = (lane >> 3) & 1;

    unsigned qa[8][4];
#pragma unroll
    for (int kk2 = 0; kk2 < 8; kk2++)
        ldsm4(qa[kk2], swz(xb, wr * 16 + arow, kk2 * 2 + achk));

    float acc[4][4] = {};
#pragma unroll
    for (int kk2 = 0; kk2 < 8; kk2++)
#pragma unroll
        for (int nb = 0; nb < 2; nb++) {
            unsigned r4[4];
            ldsm4(r4, swz(wb, wc * 32 + nb * 16 + krow, kk2 * 2 + kchk));
            mma16(acc[nb * 2 + 0], qa[kk2], &r4[0]);
            mma16(acc[nb * 2 + 1], qa[kk2], &r4[2]);
        }

    int nbase = n0 + wc * 32;
#pragma unroll
    for (int ni = 0; ni < 4; ni++) {
        int n = nbase + ni * 8 + 2 * tg;
        float b0 = g_biasf[n], b1 = g_biasf[n + 1];
        int r1 = m0 + wr * 16 + g, r2 = r1 + 8;
        if (n < 128) {
            *(unsigned*)&g_QKb[(size_t)r1 * 128 + n] = packbf(acc[ni][0] + b0, acc[ni][1] + b1);
            *(unsigned*)&g_QKb[(size_t)r2 * 128 + n] = packbf(acc[ni][2] + b0, acc[ni][3] + b1);
        } else {
            *(unsigned*)&g_Vb[(size_t)r1 * 128 + n - 128] = packbf(acc[ni][0] + b0, acc[ni][1] + b1);
            *(unsigned*)&g_Vb[(size_t)r2 * 128 + n - 128] = packbf(acc[ni][2] + b0, acc[ni][3] + b1);
        }
    }
}

// ---------------------------------------------------------------------------
// colsum[b][t] = sum_{q>=t} exp2(Q'[q].K[t]); LAST contributing block computes g_inv.
__global__ __launch_bounds__(256) void colsum_kernel() {
    const int QCHUNK = 512;
    int t0 = blockIdx.x * 64, b = blockIdx.y, qlo = blockIdx.z * QCHUNK;
    if (qlo + QCHUNK - 1 < t0) return;
    __shared__ __align__(16) __nv_bfloat16 Ksm[64 * 72];
    __shared__ __align__(16) __nv_bfloat16 Qsm[2][64 * 72];
    __shared__ float cs[64];
    __shared__ int is_last;
    const __nv_bfloat16* qk = g_QKb + (size_t)b * NT * 128;
    int tid = threadIdx.x, lane = tid & 31, w = tid >> 5;
    int g = lane >> 2, tg = lane & 3, wr = w & 1, wc = w >> 1;
    unsigned sbq = (unsigned)__cvta_generic_to_shared(&Qsm[0][0]);

    { int c = tid & 7, r0 = tid >> 3;
#pragma unroll
      for (int i = 0; i < 2; i++) { int r = r0 + 32 * i;
          *(uint4*)&Ksm[r * 72 + c * 8] = *(const uint4*)&qk[(size_t)(t0 + r) * 128 + 64 + c * 8]; } }
    if (tid < 64) cs[tid] = 0.0f;
    { int c = tid & 7, r0 = tid >> 3;
#pragma unroll
      for (int i = 0; i < 2; i++) { int r = r0 + 32 * i;
          cpa16(sbq + (r * 72 + c * 8) * 2, qk + (size_t)(qlo + r) * 128 + c * 8); } }
    cpcommit();
    __syncthreads();

    unsigned bf[2][4][2];
#pragma unroll
    for (int ni = 0; ni < 2; ni++)
#pragma unroll
        for (int kk2 = 0; kk2 < 4; kk2++) {
            int n = wc * 16 + ni * 8 + g;
            bf[ni][kk2][0] = ldu32(&Ksm[n * 72 + kk2 * 16 + 2 * tg]);
            bf[ni][kk2][1] = ldu32(&Ksm[n * 72 + kk2 * 16 + 8 + 2 * tg]);
        }

    float colacc[2][2] = {};
    int buf = 0;
    int arow = (lane & 7) + ((lane >> 3) & 1) * 8;
    int acol = (lane >> 4) * 8;
    for (int q0 = qlo; q0 < qlo + QCHUNK; q0 += 64) {
        if (q0 + 64 < qlo + QCHUNK) {
            int c = tid & 7, r0 = tid >> 3, bo = buf ^ 1;
#pragma unroll
            for (int i = 0; i < 2; i++) { int r = r0 + 32 * i;
                cpa16(sbq + bo * 9216 + (r * 72 + c * 8) * 2,
                      qk + (size_t)(q0 + 64 + r) * 128 + c * 8); }
        }
        cpcommit(); cpwait<1>(); __syncthreads();
        if (q0 + 63 >= t0) {
            unsigned qbase = sbq + buf * 9216;
            float d[2][2][4] = {};
#pragma unroll
            for (int kk2 = 0; kk2 < 4; kk2++) {
                unsigned a[2][4];
#pragma unroll
                for (int mi = 0; mi < 2; mi++) {
                    int r = wr * 32 + mi * 16 + arow;
                    ldsm4(a[mi], qbase + (r * 72 + kk2 * 16 + acol) * 2);
                }
#pragma unroll
                for (int mi = 0; mi < 2; mi++)
#pragma unroll
                    for (int ni = 0; ni < 2; ni++)
                        mma16(d[mi][ni], a[mi], bf[ni][kk2]);
            }
#pragma unroll
            for (int mi = 0; mi < 2; mi++)
#pragma unroll
                for (int ni = 0; ni < 2; ni++)
#pragma unroll
                    for (int e = 0; e < 4; e++) {
                        int row = q0 + wr * 32 + mi * 16 + g + (e >> 1) * 8;
                        int col = t0 + wc * 16 + ni * 8 + 2 * tg + (e & 1);
                        if (row >= col) colacc[ni][e & 1] += exp2f(d[mi][ni][e]);
                    }
        }
        __syncthreads();
        buf ^= 1;
    }
#pragma unroll
    for (int ni = 0; ni < 2; ni++)
#pragma unroll
        for (int j = 0; j < 2; j++) {
            float v = colacc[ni][j];
            v += __shfl_xor_sync(0xffffffffu, v, 4);
            v += __shfl_xor_sync(0xffffffffu, v, 8);
            v += __shfl_xor_sync(0xffffffffu, v, 16);
            colacc[ni][j] = v;
        }
    if (g == 0)
#pragma unroll
        for (int ni = 0; ni < 2; ni++) {
            atomicAdd(&cs[wc * 16 + ni * 8 + 2 * tg], colacc[ni][0]);
            atomicAdd(&cs[wc * 16 + ni * 8 + 2 * tg + 1], colacc[ni][1]);
        }
    __syncthreads();
    if (tid < 64) atomicAdd(&g_colsum[b * NT + t0 + tid], cs[tid]);

    __threadfence();
    __syncthreads();
    if (tid == 0) {
        int n_contrib = 8 - (t0 >> 9);
        int old = atomicAdd(&g_cnt[b * 64 + (t0 >> 6)], 1);
        is_last = (old == n_contrib - 1);
    }
    __syncthreads();
    if (is_last && tid < 64) {
        __threadfence();
        float v = __ldcg(&g_colsum[b * NT + t0 + tid]);
        g_inv[b * NT + t0 + tid] = 1.0f / (8.0f * v);
    }
}

// ---------------------------------------------------------------------------
// attn v2: ONE q-tile per 128-thread block, 2 blocks/SM. qt = 63 - xx (long first).
// smem bytes: [0,9216) Q; [9216,27648) K dbuf; [27648,62464) V dbuf; [62464,62976) inv.
// Epilogue staging reuses V region (f32 stride 133, 34048 B).
#define A2_KB 9216
#define A2_VB 27648
#define A2_IB 62464
#define A2_SMEM 62976

__global__ __launch_bounds__(128, 2) void attn_kernel(const float* __restrict__ mb,
                                                      float* __restrict__ out) {
    extern __shared__ float sm[];
    __nv_bfloat16* smb = (__nv_bfloat16*)sm;
    float* invs = (float*)((char*)sm + A2_IB);
    int qt = 63 - blockIdx.x, b = blockIdx.y;
    int q0 = qt * 64;
    const __nv_bfloat16* qk = g_QKb + (size_t)b * NT * 128;
    const __nv_bfloat16* vsb = g_Vb + (size_t)b * NT * 128;
    const float* invp = g_inv + (size_t)b * NT;
    int tid = threadIdx.x, lane = tid & 31, wg = tid >> 5;
    int g = lane >> 2, tg = lane & 3;
    unsigned sb = (unsigned)__cvta_generic_to_shared(sm);

    // Q tile (bf16, 512 16B chunks, 4/thread)
#pragma unroll
    for (int i = 0; i < 4; i++) {
        int idx = tid + 128 * i;
        int r = idx >> 3, c = idx & 7;
        *(uint4*)&smb[r * 72 + c * 8] = *(const uint4*)&qk[(size_t)(q0 + r) * 128 + c * 8];
    }
    // prefetch t=0 (K + V + inv)
#pragma unroll
    for (int i = 0; i < 4; i++) { int idx = tid + 128 * i; int r = idx >> 3, c = idx & 7;
        cpa16(sb + A2_KB + (r * 72 + c * 8) * 2, qk + (size_t)r * 128 + 64 + c * 8); }
#pragma unroll
    for (int i = 0; i < 8; i++) { int idx = tid + 128 * i; int r = idx >> 4, c = idx & 15;
        cpa16(sb + A2_VB + (r * 136 + c * 8) * 2, vsb + (size_t)r * 128 + c * 8); }
    if (tid < 16) cpa16(sb + A2_IB + tid * 16, invp + tid * 4);
    cpcommit();
    __syncthreads();

    int arow = (lane & 7) + ((lane >> 3) & 1) * 8;
    int acol = (lane >> 4) * 8;
    unsigned qa_[4][4];
#pragma unroll
    for (int kk2 = 0; kk2 < 4; kk2++)
        ldsm4(qa_[kk2], sb + ((wg * 16 + arow) * 72 + kk2 * 16 + acol) * 2);

    int krow = ((lane >> 4) << 3) + (lane & 7);
    int kcol = ((lane >> 3) & 1) * 8;
    int sub = lane >> 3, li = lane & 7;

    float acc[16][4] = {};
    int buf = 0;
    for (int tt = 0; tt <= qt; tt++) {
        if (tt < qt) {
            int t1 = (tt + 1) * 64, bo = buf ^ 1;
#pragma unroll
            for (int i = 0; i < 4; i++) { int idx = tid + 128 * i; int r = idx >> 3, c = idx & 7;
                cpa16(sb + A2_KB + bo * 9216 + (r * 72 + c * 8) * 2,
                      qk + (size_t)(t1 + r) * 128 + 64 + c * 8); }
#pragma unroll
            for (int i = 0; i < 8; i++) { int idx = tid + 128 * i; int r = idx >> 4, c = idx & 15;
                cpa16(sb + A2_VB + bo * 17408 + (r * 136 + c * 8) * 2,
                      vsb + (size_t)(t1 + r) * 128 + c * 8); }
            if (tid < 16) cpa16(sb + A2_IB + bo * 256 + tid * 16, invp + t1 + tid * 4);
        }
        cpcommit(); cpwait<1>(); __syncthreads();

        {
            unsigned kbase = sb + A2_KB + buf * 9216;
            float d[8][4] = {};
#pragma unroll
            for (int kk2 = 0; kk2 < 4; kk2++)
#pragma unroll
                for (int nb = 0; nb < 4; nb++) {
                    unsigned r4[4];
                    ldsm4(r4, kbase + ((nb * 16 + krow) * 72 + kk2 * 16 + kcol) * 2);
                    mma16(d[nb * 2 + 0], qa_[kk2], &r4[0]);
                    mma16(d[nb * 2 + 1], qa_[kk2], &r4[2]);
                }
            bool diag = (tt == qt);
            const float* ivt = invs + buf * 64;
            unsigned Af[4][4];
#pragma unroll
            for (int ni = 0; ni < 8; ni++) {
                float2 iv = *(const float2*)&ivt[ni * 8 + 2 * tg];
                float e[4];
#pragma unroll
                for (int c = 0; c < 4; c++) {
                    int row = wg * 16 + g + (c >> 1) * 8;
                    int col = ni * 8 + 2 * tg + (c & 1);
                    float v = exp2f(d[ni][c]) * ((c & 1) ? iv.y : iv.x);
                    e[c] = (diag && col > row) ? 0.0f : v;
                }
                Af[ni >> 1][(ni & 1) * 2 + 0] = packbf(e[0], e[1]);
                Af[ni >> 1][(ni & 1) * 2 + 1] = packbf(e[2], e[3]);
            }
#pragma unroll
            for (int kc = 0; kc < 4; kc++)
#pragma unroll
                for (int nj = 0; nj < 8; nj++) {
                    unsigned r4[4];
                    unsigned addr = sb + A2_VB + buf * 17408 +
                        ((kc * 16 + (sub & 1) * 8 + li) * 136 + nj * 16 + (sub >> 1) * 8) * 2;
                    ldsm4t(r4, addr);
                    mma16(acc[nj * 2 + 0], Af[kc], &r4[0]);
                    mma16(acc[nj * 2 + 1], Af[kc], &r4[2]);
                }
        }
        __syncthreads();
        buf ^= 1;
    }

    // epilogue: stage into V region (f32 stride 133), residual add, transposed write
    float* stg = (float*)((char*)sm + A2_VB);
#pragma unroll
    for (int nj = 0; nj < 16; nj++)
#pragma unroll
        for (int c = 0; c < 4; c++) {
            int row = wg * 16 + g + (c >> 1) * 8;
            int col = nj * 8 + 2 * tg + (c & 1);
            stg[row * 133 + col] = acc[nj][c];
        }
    __syncthreads();
    {
        int qq = tid & 63, db = tid >> 6;
        const float* xin = mb + (size_t)b * ND * NT;
        float* o = out + (size_t)b * ND * NT;
#pragma unroll
        for (int i = 0; i < 64; i++) {
            int d_ = db + i * 2;
            o[d_ * NT + q0 + qq] = xin[d_ * NT + q0 + qq] + stg[qq * 133 + d_];
        }
    }
}

// ---------------------------------------------------------------------------
extern "C" void kernel_launch(void* const* d_in, const int* in_sizes, int n_in,
                              void* d_out, int out_size) {
    const float* mb = (const float*)d_in[0];
    const float* Wk = (const float*)d_in[1];
    const float* bk = (const float*)d_in[2];
    const float* Wq = (const float*)d_in[3];
    const float* bq = (const float*)d_in[4];
    const float* Wv = (const float*)d_in[5];
    const float* bv = (const float*)d_in[6];
    float* out = (float*)d_out;

    cudaFuncSetAttribute(attn_kernel, cudaFuncAttributeMaxDynamicSharedMemorySize, A2_SMEM);

    wconv_kernel<<<128, 256>>>(Wq, bq, Wk, bk, Wv, bv);
    qkv_kernel<<<dim3(2, 512), 256>>>(mb);
    colsum_kernel<<<dim3(64, 4, 8), 256>>>();
    attn_kernel<<<dim3(64, 4), 128, A2_SMEM>>>(mb, out);
}

// round 16
// speedup vs baseline: 1.2578x; 1.2578x over previous
#include <cuda_runtime.h>
#include <cuda_bf16.h>
#include <math.h>

#define NB 4
#define ND 128
#define NT 4096
#define LOG2E 1.4426950408889634f

__device__ __nv_bfloat16 g_QKb[NB * NT * 128];  // per row: [Q(64)*log2e | K(64)] bf16
__device__ unsigned short g_Vh[NB * NT * 128];  // V fp16 bits
__device__ __nv_bfloat16 g_Wb[256 * 128];       // [Wq*log2e | Wk | Wv] bf16
__device__ float g_biasf[256];                  // [bq*log2e | bk | bv]
__device__ float g_colsum[NB * NT];
__device__ float g_l2i[NB * NT];                // log2(1/(8*colsum)) = -3 - log2(colsum)
__device__ int   g_cnt[NB * 64];                // per t-tile completion counters

// ---------------------------------------------------------------------------
__device__ __forceinline__ void mma16(float* d, const unsigned* a, const unsigned* b) {
    asm volatile(
        "mma.sync.aligned.m16n8k16.row.col.f32.bf16.bf16.f32 "
        "{%0,%1,%2,%3}, {%4,%5,%6,%7}, {%8,%9}, {%0,%1,%2,%3};\n"
        : "+f"(d[0]), "+f"(d[1]), "+f"(d[2]), "+f"(d[3])
        : "r"(a[0]), "r"(a[1]), "r"(a[2]), "r"(a[3]), "r"(b[0]), "r"(b[1]));
}
__device__ __forceinline__ void mma16h(float* d, const unsigned* a, const unsigned* b) {
    asm volatile(
        "mma.sync.aligned.m16n8k16.row.col.f32.f16.f16.f32 "
        "{%0,%1,%2,%3}, {%4,%5,%6,%7}, {%8,%9}, {%0,%1,%2,%3};\n"
        : "+f"(d[0]), "+f"(d[1]), "+f"(d[2]), "+f"(d[3])
        : "r"(a[0]), "r"(a[1]), "r"(a[2]), "r"(a[3]), "r"(b[0]), "r"(b[1]));
}
__device__ __forceinline__ unsigned packbf(float lo, float hi) {
    unsigned r;
    asm("cvt.rn.bf16x2.f32 %0, %1, %2;" : "=r"(r) : "f"(hi), "f"(lo));
    return r;
}
__device__ __forceinline__ unsigned packh(float lo, float hi) {
    unsigned r;
    asm("cvt.rn.f16x2.f32 %0, %1, %2;" : "=r"(r) : "f"(hi), "f"(lo));
    return r;
}
__device__ __forceinline__ unsigned ex2h2(unsigned x) {
    unsigned r;
    asm("ex2.approx.f16x2 %0, %1;" : "=r"(r) : "r"(x));
    return r;
}
__device__ __forceinline__ void ldsm4(unsigned* r, unsigned addr) {
    asm volatile("ldmatrix.sync.aligned.m8n8.x4.shared.b16 {%0,%1,%2,%3}, [%4];"
                 : "=r"(r[0]), "=r"(r[1]), "=r"(r[2]), "=r"(r[3]) : "r"(addr));
}
__device__ __forceinline__ void ldsm4t(unsigned* r, unsigned addr) {
    asm volatile("ldmatrix.sync.aligned.m8n8.x4.trans.shared.b16 {%0,%1,%2,%3}, [%4];"
                 : "=r"(r[0]), "=r"(r[1]), "=r"(r[2]), "=r"(r[3]) : "r"(addr));
}
__device__ __forceinline__ void cpa16(unsigned saddr, const void* gsrc) {
    asm volatile("cp.async.cg.shared.global [%0], [%1], 16;" :: "r"(saddr), "l"(gsrc));
}
__device__ __forceinline__ void cpcommit() { asm volatile("cp.async.commit_group;"); }
template <int N>
__device__ __forceinline__ void cpwait() { asm volatile("cp.async.wait_group %0;" :: "n"(N)); }
__device__ __forceinline__ unsigned ldu32(const __nv_bfloat16* p) { return *(const unsigned*)p; }
__device__ __forceinline__ unsigned swz(unsigned base, int row, int chunk) {
    return base + ((row * 16 + (chunk ^ (row & 7))) << 4);
}

// ---------------------------------------------------------------------------
// Convert weights to bf16 once; fold log2e into Wq/bq.
__global__ void wconv_kernel(const float* __restrict__ Wq, const float* __restrict__ bq,
                             const float* __restrict__ Wk, const float* __restrict__ bk,
                             const float* __restrict__ Wv, const float* __restrict__ bv) {
    int i = blockIdx.x * 256 + threadIdx.x;      // [0, 32768)
    int n = i >> 7, d = i & 127;
    float v;
    if (n < 64)       v = Wq[n * 128 + d] * LOG2E;
    else if (n < 128) v = Wk[(n - 64) * 128 + d];
    else              v = Wv[(n - 128) * 128 + d];
    g_Wb[i] = __float2bfloat16(v);
    if (i < 256) {
        float bb;
        if (i < 64)       bb = bq[i] * LOG2E;
        else if (i < 128) bb = bk[i - 64];
        else              bb = bv[i - 128];
        g_biasf[i] = bb;
    }
}

// ---------------------------------------------------------------------------
// QKV: grid (2 n-halves, 512 m-half-tiles). Q|K bf16, V fp16.
__global__ __launch_bounds__(256) void qkv_kernel(const float* __restrict__ mb) {
    __shared__ __align__(16) __nv_bfloat16 Xb[32 * 128];   // swizzled [r][d]
    __shared__ __align__(16) __nv_bfloat16 Wb[128 * 128];  // swizzled [n][d]
    int n0 = blockIdx.x * 128;
    int m0 = blockIdx.y * 32;
    int b = m0 >> 12, t0 = m0 & (NT - 1);
    const float* x = mb + (size_t)b * ND * NT;
    int tid = threadIdx.x, lane = tid & 31, w = tid >> 5;
    int g = lane >> 2, tg = lane & 3;
    int wr = w & 1, wc = w >> 1;

    if (blockIdx.x == 0) {
        if (tid < 32) g_colsum[m0 + tid] = 0.0f;
        if (tid == 32 && !(m0 & 32)) g_cnt[m0 >> 6] = 0;
    }

    unsigned xb = (unsigned)__cvta_generic_to_shared(Xb);
    unsigned wb = (unsigned)__cvta_generic_to_shared(Wb);

#pragma unroll
    for (int i = 0; i < 8; i++) {
        int idx = tid + 256 * i;
        int n = idx >> 4, c = idx & 15;
        cpa16(swz(wb, n, c), &g_Wb[(size_t)(n0 + n) * 128 + c * 8]);
    }
    cpcommit();

#pragma unroll
    for (int i = 0; i < 8; i++) {
        int idx = tid + 256 * i;
        int r = idx & 31, d2 = idx >> 5;
        float v0 = x[(2 * d2) * NT + t0 + r];
        float v1 = x[(2 * d2 + 1) * NT + t0 + r];
        *(unsigned*)&Xb[(r * 16 + ((d2 >> 2) ^ (r & 7))) * 8 + (d2 & 3) * 2] = packbf(v0, v1);
    }
    cpwait<0>();
    __syncthreads();

    int arow = (lane & 7) + ((lane >> 3) & 1) * 8;
    int achk = lane >> 4;
    int krow = ((lane >> 4) << 3) + (lane & 7);
    int kchk = (lane >> 3) & 1;

    unsigned qa[8][4];
#pragma unroll
    for (int kk2 = 0; kk2 < 8; kk2++)
        ldsm4(qa[kk2], swz(xb, wr * 16 + arow, kk2 * 2 + achk));

    float acc[4][4] = {};
#pragma unroll
    for (int kk2 = 0; kk2 < 8; kk2++)
#pragma unroll
        for (int nb = 0; nb < 2; nb++) {
            unsigned r4[4];
            ldsm4(r4, swz(wb, wc * 32 + nb * 16 + krow, kk2 * 2 + kchk));
            mma16(acc[nb * 2 + 0], qa[kk2], &r4[0]);
            mma16(acc[nb * 2 + 1], qa[kk2], &r4[2]);
        }

    int nbase = n0 + wc * 32;
#pragma unroll
    for (int ni = 0; ni < 4; ni++) {
        int n = nbase + ni * 8 + 2 * tg;
        float b0 = g_biasf[n], b1 = g_biasf[n + 1];
        int r1 = m0 + wr * 16 + g, r2 = r1 + 8;
        if (n < 128) {
            *(unsigned*)&g_QKb[(size_t)r1 * 128 + n] = packbf(acc[ni][0] + b0, acc[ni][1] + b1);
            *(unsigned*)&g_QKb[(size_t)r2 * 128 + n] = packbf(acc[ni][2] + b0, acc[ni][3] + b1);
        } else {
            *(unsigned*)&g_Vh[(size_t)r1 * 128 + n - 128] = packh(acc[ni][0] + b0, acc[ni][1] + b1);
            *(unsigned*)&g_Vh[(size_t)r2 * 128 + n - 128] = packh(acc[ni][2] + b0, acc[ni][3] + b1);
        }
    }
}

// ---------------------------------------------------------------------------
// colsum[b][t] = sum_{q>=t} exp2(Q'[q].K[t]); LAST contributing block writes g_l2i.
__global__ __launch_bounds__(256) void colsum_kernel() {
    const int QCHUNK = 512;
    int t0 = blockIdx.x * 64, b = blockIdx.y, qlo = blockIdx.z * QCHUNK;
    if (qlo + QCHUNK - 1 < t0) return;
    __shared__ __align__(16) __nv_bfloat16 Ksm[64 * 72];
    __shared__ __align__(16) __nv_bfloat16 Qsm[2][64 * 72];
    __shared__ float cs[64];
    __shared__ int is_last;
    const __nv_bfloat16* qk = g_QKb + (size_t)b * NT * 128;
    int tid = threadIdx.x, lane = tid & 31, w = tid >> 5;
    int g = lane >> 2, tg = lane & 3, wr = w & 1, wc = w >> 1;
    unsigned sbq = (unsigned)__cvta_generic_to_shared(&Qsm[0][0]);

    { int c = tid & 7, r0 = tid >> 3;
#pragma unroll
      for (int i = 0; i < 2; i++) { int r = r0 + 32 * i;
          *(uint4*)&Ksm[r * 72 + c * 8] = *(const uint4*)&qk[(size_t)(t0 + r) * 128 + 64 + c * 8]; } }
    if (tid < 64) cs[tid] = 0.0f;
    { int c = tid & 7, r0 = tid >> 3;
#pragma unroll
      for (int i = 0; i < 2; i++) { int r = r0 + 32 * i;
          cpa16(sbq + (r * 72 + c * 8) * 2, qk + (size_t)(qlo + r) * 128 + c * 8); } }
    cpcommit();
    __syncthreads();

    unsigned bf[2][4][2];
#pragma unroll
    for (int ni = 0; ni < 2; ni++)
#pragma unroll
        for (int kk2 = 0; kk2 < 4; kk2++) {
            int n = wc * 16 + ni * 8 + g;
            bf[ni][kk2][0] = ldu32(&Ksm[n * 72 + kk2 * 16 + 2 * tg]);
            bf[ni][kk2][1] = ldu32(&Ksm[n * 72 + kk2 * 16 + 8 + 2 * tg]);
        }

    float colacc[2][2] = {};
    int buf = 0;
    int arow = (lane & 7) + ((lane >> 3) & 1) * 8;
    int acol = (lane >> 4) * 8;
    for (int q0 = qlo; q0 < qlo + QCHUNK; q0 += 64) {
        if (q0 + 64 < qlo + QCHUNK) {
            int c = tid & 7, r0 = tid >> 3, bo = buf ^ 1;
#pragma unroll
            for (int i = 0; i < 2; i++) { int r = r0 + 32 * i;
                cpa16(sbq + bo * 9216 + (r * 72 + c * 8) * 2,
                      qk + (size_t)(q0 + 64 + r) * 128 + c * 8); }
        }
        cpcommit(); cpwait<1>(); __syncthreads();
        if (q0 + 63 >= t0) {
            unsigned qbase = sbq + buf * 9216;
            float d[2][2][4] = {};
#pragma unroll
            for (int kk2 = 0; kk2 < 4; kk2++) {
                unsigned a[2][4];
#pragma unroll
                for (int mi = 0; mi < 2; mi++) {
                    int r = wr * 32 + mi * 16 + arow;
                    ldsm4(a[mi], qbase + (r * 72 + kk2 * 16 + acol) * 2);
                }
#pragma unroll
                for (int mi = 0; mi < 2; mi++)
#pragma unroll
                    for (int ni = 0; ni < 2; ni++)
                        mma16(d[mi][ni], a[mi], bf[ni][kk2]);
            }
#pragma unroll
            for (int mi = 0; mi < 2; mi++)
#pragma unroll
                for (int ni = 0; ni < 2; ni++)
#pragma unroll
                    for (int e = 0; e < 4; e++) {
                        int row = q0 + wr * 32 + mi * 16 + g + (e >> 1) * 8;
                        int col = t0 + wc * 16 + ni * 8 + 2 * tg + (e & 1);
                        if (row >= col) colacc[ni][e & 1] += exp2f(d[mi][ni][e]);
                    }
        }
        __syncthreads();
        buf ^= 1;
    }
#pragma unroll
    for (int ni = 0; ni < 2; ni++)
#pragma unroll
        for (int j = 0; j < 2; j++) {
            float v = colacc[ni][j];
            v += __shfl_xor_sync(0xffffffffu, v, 4);
            v += __shfl_xor_sync(0xffffffffu, v, 8);
            v += __shfl_xor_sync(0xffffffffu, v, 16);
            colacc[ni][j] = v;
        }
    if (g == 0)
#pragma unroll
        for (int ni = 0; ni < 2; ni++) {
            atomicAdd(&cs[wc * 16 + ni * 8 + 2 * tg], colacc[ni][0]);
            atomicAdd(&cs[wc * 16 + ni * 8 + 2 * tg + 1], colacc[ni][1]);
        }
    __syncthreads();
    if (tid < 64) atomicAdd(&g_colsum[b * NT + t0 + tid], cs[tid]);

    __threadfence();
    __syncthreads();
    if (tid == 0) {
        int n_contrib = 8 - (t0 >> 9);
        int old = atomicAdd(&g_cnt[b * 64 + (t0 >> 6)], 1);
        is_last = (old == n_contrib - 1);
    }
    __syncthreads();
    if (is_last && tid < 64) {
        __threadfence();
        float v = __ldcg(&g_colsum[b * NT + t0 + tid]);
        g_l2i[b * NT + t0 + tid] = -3.0f - __log2f(v);
    }
}

// ---------------------------------------------------------------------------
// attn (R14 structure): block xx handles q-tiles (xx, 63-xx). Warps 0-3 A, 4-7 B.
// E = ex2.approx.f16x2(S + l2i[t]) in fp16; EV mma f16.
#define AT_KB 18432
#define AT_VB 36864
#define AT_IB 71680
#define ATT_SMEM 72192

__global__ __launch_bounds__(256, 1) void attn_kernel(const float* __restrict__ mb,
                                                      float* __restrict__ out) {
    extern __shared__ float sm[];
    __nv_bfloat16* smb = (__nv_bfloat16*)sm;
    float* invs = (float*)((char*)sm + AT_IB);
    int xx = blockIdx.x, b = blockIdx.y;
    int qtA = xx, qtB = 63 - xx;
    int q0A = qtA * 64, q0B = qtB * 64;
    const __nv_bfloat16* qk = g_QKb + (size_t)b * NT * 128;
    const unsigned short* vsb = g_Vh + (size_t)b * NT * 128;
    const float* invp = g_l2i + (size_t)b * NT;
    int tid = threadIdx.x, lane = tid & 31, w = tid >> 5;
    int g = lane >> 2, tg = lane & 3;
    int gid = w >> 2, wg = w & 3;
    int myqt = gid ? qtB : qtA;
    unsigned sb = (unsigned)__cvta_generic_to_shared(sm);

#pragma unroll
    for (int i = 0; i < 4; i++) {
        int idx = tid + 256 * i;
        int grp = idx >> 9, rem = idx & 511, r = rem >> 3, c = rem & 7;
        int q0g = grp ? q0B : q0A;
        *(uint4*)&smb[grp * 4608 + r * 72 + c * 8] =
            *(const uint4*)&qk[(size_t)(q0g + r) * 128 + c * 8];
    }
#pragma unroll
    for (int i = 0; i < 2; i++) { int idx = tid + 256 * i; int r = idx >> 3, c = idx & 7;
        cpa16(sb + AT_KB + (r * 72 + c * 8) * 2, qk + (size_t)r * 128 + 64 + c * 8); }
#pragma unroll
    for (int i = 0; i < 4; i++) { int idx = tid + 256 * i; int r = idx >> 4, c = idx & 15;
        cpa16(sb + AT_VB + (r * 136 + c * 8) * 2, vsb + (size_t)r * 128 + c * 8); }
    if (tid < 16) cpa16(sb + AT_IB + tid * 16, invp + tid * 4);
    cpcommit();
    __syncthreads();

    int arow = (lane & 7) + ((lane >> 3) & 1) * 8;
    int acol = (lane >> 4) * 8;
    unsigned qbase = sb + gid * 9216;
    unsigned qa_[4][4];
#pragma unroll
    for (int kk2 = 0; kk2 < 4; kk2++)
        ldsm4(qa_[kk2], qbase + ((wg * 16 + arow) * 72 + kk2 * 16 + acol) * 2);

    int krow = ((lane >> 4) << 3) + (lane & 7);
    int kcol = ((lane >> 3) & 1) * 8;

    float acc[16][4] = {};
    int buf = 0;
    int sub = lane >> 3, li = lane & 7;
    for (int tt = 0; tt <= qtB; tt++) {
        if (tt < qtB) {
            int t1 = (tt + 1) * 64, bo = buf ^ 1;
#pragma unroll
            for (int i = 0; i < 2; i++) { int idx = tid + 256 * i; int r = idx >> 3, c = idx & 7;
                cpa16(sb + AT_KB + bo * 9216 + (r * 72 + c * 8) * 2,
                      qk + (size_t)(t1 + r) * 128 + 64 + c * 8); }
#pragma unroll
            for (int i = 0; i < 4; i++) { int idx = tid + 256 * i; int r = idx >> 4, c = idx & 15;
                cpa16(sb + AT_VB + bo * 17408 + (r * 136 + c * 8) * 2,
                      vsb + (size_t)(t1 + r) * 128 + c * 8); }
            if (tid < 16) cpa16(sb + AT_IB + bo * 256 + tid * 16, invp + t1 + tid * 4);
        }
        cpcommit(); cpwait<1>(); __syncthreads();

        if (tt <= myqt) {
            unsigned kbase = sb + AT_KB + buf * 9216;
            float d[8][4] = {};
#pragma unroll
            for (int kk2 = 0; kk2 < 4; kk2++)
#pragma unroll
                for (int nb = 0; nb < 4; nb++) {
                    unsigned r4[4];
                    ldsm4(r4, kbase + ((nb * 16 + krow) * 72 + kk2 * 16 + kcol) * 2);
                    mma16(d[nb * 2 + 0], qa_[kk2], &r4[0]);
                    mma16(d[nb * 2 + 1], qa_[kk2], &r4[2]);
                }
            bool diag = (tt == myqt);
            const float* ivt = invs + buf * 64;
            unsigned Af[4][4];
#pragma unroll
            for (int ni = 0; ni < 8; ni++) {
                float2 iv = *(const float2*)&ivt[ni * 8 + 2 * tg];
                float e[4];
#pragma unroll
                for (int c = 0; c < 4; c++) {
                    int row = wg * 16 + g + (c >> 1) * 8;
                    int col = ni * 8 + 2 * tg + (c & 1);
                    float v = d[ni][c] + ((c & 1) ? iv.y : iv.x);
                    e[c] = (diag && col > row) ? -60000.0f : v;
                }
                Af[ni >> 1][(ni & 1) * 2 + 0] = ex2h2(packh(e[0], e[1]));
                Af[ni >> 1][(ni & 1) * 2 + 1] = ex2h2(packh(e[2], e[3]));
            }
#pragma unroll
            for (int kc = 0; kc < 4; kc++)
#pragma unroll
                for (int nj = 0; nj < 8; nj++) {
                    unsigned r4[4];
                    unsigned addr = sb + AT_VB + buf * 17408 +
                        ((kc * 16 + (sub & 1) * 8 + li) * 136 + nj * 16 + (sub >> 1) * 8) * 2;
                    ldsm4t(r4, addr);
                    mma16h(acc[nj * 2 + 0], Af[kc], &r4[0]);
                    mma16h(acc[nj * 2 + 1], Af[kc], &r4[2]);
                }
        }
        __syncthreads();
        buf ^= 1;
    }

    float* stg = gid ? (sm + 8704) : sm;
#pragma unroll
    for (int nj = 0; nj < 16; nj++)
#pragma unroll
        for (int c = 0; c < 4; c++) {
            int row = wg * 16 + g + (c >> 1) * 8;
            int col = nj * 8 + 2 * tg + (c & 1);
            stg[row * 133 + col] = acc[nj][c];
        }
    __syncthreads();
    {
        int gw = tid >> 7, gtid = tid & 127;
        int qq = gtid & 63, db = gtid >> 6;
        const float* s2 = gw ? (sm + 8704) : sm;
        int q0w = gw ? q0B : q0A;
        const float* xin = mb + (size_t)b * ND * NT;
        float* o = out + (size_t)b * ND * NT;
#pragma unroll
        for (int i = 0; i < 64; i++) {
            int d_ = db + i * 2;
            o[d_ * NT + q0w + qq] = xin[d_ * NT + q0w + qq] + s2[qq * 133 + d_];
        }
    }
}

// ---------------------------------------------------------------------------
extern "C" void kernel_launch(void* const* d_in, const int* in_sizes, int n_in,
                              void* d_out, int out_size) {
    const float* mb = (const float*)d_in[0];
    const float* Wk = (const float*)d_in[1];
    const float* bk = (const float*)d_in[2];
    const float* Wq = (const float*)d_in[3];
    const float* bq = (const float*)d_in[4];
    const float* Wv = (const float*)d_in[5];
    const float* bv = (const float*)d_in[6];
    float* out = (float*)d_out;

    cudaFuncSetAttribute(attn_kernel, cudaFuncAttributeMaxDynamicSharedMemorySize, ATT_SMEM);

    wconv_kernel<<<128, 256>>>(Wq, bq, Wk, bk, Wv, bv);
    qkv_kernel<<<dim3(2, 512), 256>>>(mb);
    colsum_kernel<<<dim3(64, 4, 8), 256>>>();
    attn_kernel<<<dim3(32, 4), 256, ATT_SMEM>>>(mb, out);
}